// round 4
// baseline (speedup 1.0000x reference)
#include <cuda_runtime.h>
#include <math.h>
#include <stdint.h>

#define DIM   192
#define HEADS 6
#define HD    32
#define NWIN  1024          // 4 * 16 * 16
#define NQTOK 65536         // 1024 * 64  (== B*L)
#define NKVTOK 262144       // 1024 * 256
#define SCALE 0.17677669529663687f   // 32^-0.5

// ---------------- scratch (device globals; no runtime allocation) ----------------
__device__ float g_xn [(size_t)NQTOK * DIM];        // LN1 output, window order
__device__ float g_q  [(size_t)NQTOK * DIM];        // q projection, window order
__device__ float g_kv [(size_t)NKVTOK * 2 * DIM];   // k | v, window order
__device__ float g_ao [(size_t)NQTOK * DIM];        // attention output, window order
__device__ float g_x1 [(size_t)NQTOK * DIM];        // x after first residual, natural order
__device__ float g_ln2[(size_t)NQTOK * DIM];        // LN2 output
__device__ float g_h  [(size_t)NQTOK * 4 * DIM];    // gelu(fc1) output

// ---------------- LayerNorm (one token per block, 192 threads) ----------------
// MODE 0: read x in natural order, write in 8x8-window-partition order.
// MODE 1: natural in, natural out.
template<int MODE>
__global__ __launch_bounds__(192) void ln_kernel(
    const float* __restrict__ x, const float* __restrict__ w,
    const float* __restrict__ b, float* __restrict__ out)
{
    int tok = blockIdx.x;
    int tid = threadIdx.x;
    int in_row, out_row;
    if (MODE == 0) {
        int win = tok >> 6, t = tok & 63;
        int bb = win >> 8, wi = win & 255;
        int wr = wi >> 4,  wc = wi & 15;
        int r  = t  >> 3,  c  = t  & 7;
        in_row  = bb * 16384 + (wr * 8 + r) * 128 + (wc * 8 + c);
        out_row = tok;
    } else {
        in_row = out_row = tok;
    }
    float v = x[(size_t)in_row * DIM + tid];
    float s1 = v, s2 = v * v;
    #pragma unroll
    for (int off = 16; off; off >>= 1) {
        s1 += __shfl_xor_sync(0xffffffffu, s1, off);
        s2 += __shfl_xor_sync(0xffffffffu, s2, off);
    }
    __shared__ float red[12];
    int warp = tid >> 5, lane = tid & 31;
    if (lane == 0) { red[warp] = s1; red[6 + warp] = s2; }
    __syncthreads();
    if (tid == 0) {
        float a = 0.f, c2 = 0.f;
        #pragma unroll
        for (int i = 0; i < 6; i++) { a += red[i]; c2 += red[6 + i]; }
        red[0] = a; red[6] = c2;
    }
    __syncthreads();
    float mean = red[0] * (1.0f / 192.0f);
    float var  = red[6] * (1.0f / 192.0f) - mean * mean;
    float rstd = rsqrtf(var + 1e-5f);
    out[(size_t)out_row * DIM + tid] = (v - mean) * rstd * w[tid] + b[tid];
}

// ---------------- Generic tiled SGEMM: C = A @ W^T + bias, with epilogues ----------
// W is (N, K) row-major. A rows row-major stride K.
// MODE 0: plain A, plain store
// MODE 1: A rows gathered through 16x16 window partition of x2, plain store
// MODE 2: plain A (window order), epilogue: + add[nat_row] (shortcut), store at
//         window-reversed natural row
// MODE 3: plain A, epilogue exact gelu, plain store
// MODE 4: plain A, epilogue + add[row], plain store
template<int MODE, int N, int K>
__global__ __launch_bounds__(256) void gemm_kernel(
    const float* __restrict__ A, const float* __restrict__ W,
    const float* __restrict__ bias, float* __restrict__ C,
    const float* __restrict__ add)
{
    constexpr int BM = 128, BN = 64, BK = 16;
    __shared__ float As[BK][BM + 4];
    __shared__ float Bs[BK][BN + 4];

    int tid = threadIdx.x;
    int mb = blockIdx.x * BM, nb = blockIdx.y * BN;

    int r0 = tid >> 2;
    int kq = (tid & 3) * 4;

    int arow0 = mb + r0;
    int arow1 = mb + r0 + 64;
    int src0, src1;
    if (MODE == 1) {
        // window-order kv token -> natural x2 row
        int win = arow0 >> 8, t = arow0 & 255;
        int bb = win >> 8, wi = win & 255;
        int wr = wi >> 4,  wc = wi & 15;
        int rr = t  >> 4,  cc = t  & 15;
        src0 = bb * 65536 + (wr * 16 + rr) * 256 + (wc * 16 + cc);
        win = arow1 >> 8; t = arow1 & 255;
        bb = win >> 8; wi = win & 255;
        wr = wi >> 4;  wc = wi & 15;
        rr = t  >> 4;  cc = t  & 15;
        src1 = bb * 65536 + (wr * 16 + rr) * 256 + (wc * 16 + cc);
    } else {
        src0 = arow0; src1 = arow1;
    }
    const float* ap0 = A + (size_t)src0 * K + kq;
    const float* ap1 = A + (size_t)src1 * K + kq;
    int bn = tid >> 2;
    const float* wp = W + (size_t)(nb + bn) * K + kq;

    float acc[8][4];
    #pragma unroll
    for (int i = 0; i < 8; i++)
        #pragma unroll
        for (int j = 0; j < 4; j++) acc[i][j] = 0.f;

    int ty = tid >> 4, tx = tid & 15;

    for (int k0 = 0; k0 < K; k0 += BK) {
        float4 a0 = *(const float4*)(ap0 + k0);
        float4 a1 = *(const float4*)(ap1 + k0);
        float4 bv = *(const float4*)(wp + k0);
        As[kq + 0][r0] = a0.x; As[kq + 1][r0] = a0.y;
        As[kq + 2][r0] = a0.z; As[kq + 3][r0] = a0.w;
        As[kq + 0][r0 + 64] = a1.x; As[kq + 1][r0 + 64] = a1.y;
        As[kq + 2][r0 + 64] = a1.z; As[kq + 3][r0 + 64] = a1.w;
        Bs[kq + 0][bn] = bv.x; Bs[kq + 1][bn] = bv.y;
        Bs[kq + 2][bn] = bv.z; Bs[kq + 3][bn] = bv.w;
        __syncthreads();
        #pragma unroll
        for (int k = 0; k < BK; k++) {
            float ra[8], rb[4];
            *(float4*)&ra[0] = *(const float4*)&As[k][ty * 8];
            *(float4*)&ra[4] = *(const float4*)&As[k][ty * 8 + 4];
            *(float4*)&rb[0] = *(const float4*)&Bs[k][tx * 4];
            #pragma unroll
            for (int i = 0; i < 8; i++)
                #pragma unroll
                for (int j = 0; j < 4; j++)
                    acc[i][j] += ra[i] * rb[j];
        }
        __syncthreads();
    }

    float4 bb4 = *(const float4*)(bias + nb + tx * 4);
    #pragma unroll
    for (int i = 0; i < 8; i++) {
        int row = mb + ty * 8 + i;
        int col = nb + tx * 4;
        float4 o;
        o.x = acc[i][0] + bb4.x; o.y = acc[i][1] + bb4.y;
        o.z = acc[i][2] + bb4.z; o.w = acc[i][3] + bb4.w;
        if (MODE == 2) {
            int win = row >> 6, t = row & 63;
            int bI = win >> 8, wi = win & 255;
            int wr = wi >> 4,  wc = wi & 15;
            int rr = t  >> 3,  cc = t  & 7;
            int nat = bI * 16384 + (wr * 8 + rr) * 128 + (wc * 8 + cc);
            const float4 s = *(const float4*)(add + (size_t)nat * DIM + col);
            o.x += s.x; o.y += s.y; o.z += s.z; o.w += s.w;
            *(float4*)(C + (size_t)nat * DIM + col) = o;
        } else if (MODE == 3) {
            o.x = 0.5f * o.x * (1.0f + erff(o.x * 0.70710678118654752f));
            o.y = 0.5f * o.y * (1.0f + erff(o.y * 0.70710678118654752f));
            o.z = 0.5f * o.z * (1.0f + erff(o.z * 0.70710678118654752f));
            o.w = 0.5f * o.w * (1.0f + erff(o.w * 0.70710678118654752f));
            *(float4*)(C + (size_t)row * N + col) = o;
        } else if (MODE == 4) {
            const float4 s = *(const float4*)(add + (size_t)row * N + col);
            o.x += s.x; o.y += s.y; o.z += s.z; o.w += s.w;
            *(float4*)(C + (size_t)row * N + col) = o;
        } else {
            *(float4*)(C + (size_t)row * N + col) = o;
        }
    }
}

// ---------------- Attention: one block per (window, head) ----------------
// q (64x32, pre-scaled), kT (32x256 padded), v (256x32), S (64x256), bias (529)
// all in shared. 256 threads, warp w owns score rows w*8..w*8+7 end-to-end.
#define KT_STRIDE 260
#define ATTN_SMEM_FLOATS (2048 + 32 * KT_STRIDE + 8192 + 16384 + 532)

__global__ __launch_bounds__(256) void attn_kernel(const float* __restrict__ rel_bias)
{
    extern __shared__ float sm[];
    float* sQ  = sm;                      // 64*32   = 2048
    float* sKT = sm + 2048;               // 32*260  = 8320
    float* sV  = sKT + 32 * KT_STRIDE;    // 256*32  = 8192
    float* sS  = sV + 8192;               // 64*256  = 16384
    float* sB  = sS + 16384;              // 529 (+pad)

    int win = blockIdx.x, h = blockIdx.y;
    int tid = threadIdx.x;

    for (int r = tid; r < 529; r += 256) sB[r] = rel_bias[r * HEADS + h];

    const float* qb = g_q + (size_t)win * 64 * DIM + h * HD;
    for (int idx = tid; idx < 64 * 32; idx += 256) {
        int i = idx >> 5, d = idx & 31;
        sQ[idx] = qb[i * DIM + d] * SCALE;
    }
    const float* kb = g_kv + (size_t)win * 256 * (2 * DIM) + h * HD;
    const float* vb = kb + DIM;
    for (int idx = tid; idx < 256 * 32; idx += 256) {
        int j = idx >> 5, d = idx & 31;
        sKT[d * KT_STRIDE + j] = kb[(size_t)j * (2 * DIM) + d];
        sV[idx]                = vb[(size_t)j * (2 * DIM) + d];
    }
    __syncthreads();

    int warp = tid >> 5, lane = tid & 31;

    // ---- S = (q*scale) @ k^T + bias : warp w -> rows w*8..+7, lane -> j = lane*8..+7
    for (int r = 0; r < 8; r++) {
        int i = warp * 8 + r;
        float acc[8] = {0.f, 0.f, 0.f, 0.f, 0.f, 0.f, 0.f, 0.f};
        #pragma unroll
        for (int kk = 0; kk < 32; kk++) {
            float qv = sQ[i * 32 + kk];
            float4 k0 = *(const float4*)&sKT[kk * KT_STRIDE + lane * 8];
            float4 k1 = *(const float4*)&sKT[kk * KT_STRIDE + lane * 8 + 4];
            acc[0] += qv * k0.x; acc[1] += qv * k0.y;
            acc[2] += qv * k0.z; acc[3] += qv * k0.w;
            acc[4] += qv * k1.x; acc[5] += qv * k1.y;
            acc[6] += qv * k1.z; acc[7] += qv * k1.w;
        }
        int r1 = i >> 3, c1 = i & 7;
        #pragma unroll
        for (int u = 0; u < 8; u++) {
            int j = lane * 8 + u;
            int ridx = (r1 - (j >> 4) + 15) * 23 + (c1 - (j & 15) + 15);
            sS[i * 256 + j] = acc[u] + sB[ridx];
        }
    }
    __syncwarp();

    // ---- row softmax (warp-local rows)
    for (int r = 0; r < 8; r++) {
        int i = warp * 8 + r;
        float* row = sS + i * 256;
        float vals[8];
        float m = -1e30f;
        #pragma unroll
        for (int u = 0; u < 8; u++) { vals[u] = row[lane + u * 32]; m = fmaxf(m, vals[u]); }
        #pragma unroll
        for (int off = 16; off; off >>= 1) m = fmaxf(m, __shfl_xor_sync(0xffffffffu, m, off));
        float s = 0.f;
        #pragma unroll
        for (int u = 0; u < 8; u++) { vals[u] = __expf(vals[u] - m); s += vals[u]; }
        #pragma unroll
        for (int off = 16; off; off >>= 1) s += __shfl_xor_sync(0xffffffffu, s, off);
        float inv = 1.0f / s;
        #pragma unroll
        for (int u = 0; u < 8; u++) row[lane + u * 32] = vals[u] * inv;
    }
    __syncwarp();

    // ---- O = P @ v : warp w rows, lane -> output dim d
    float acc[8] = {0.f, 0.f, 0.f, 0.f, 0.f, 0.f, 0.f, 0.f};
    int i0 = warp * 8;
    for (int j4 = 0; j4 < 64; j4++) {
        int j = j4 * 4;
        float v0 = sV[(j + 0) * 32 + lane];
        float v1 = sV[(j + 1) * 32 + lane];
        float v2 = sV[(j + 2) * 32 + lane];
        float v3 = sV[(j + 3) * 32 + lane];
        #pragma unroll
        for (int rr = 0; rr < 8; rr++) {
            float4 p = *(const float4*)&sS[(i0 + rr) * 256 + j];
            acc[rr] += p.x * v0 + p.y * v1 + p.z * v2 + p.w * v3;
        }
    }
    float* ob = g_ao + (size_t)win * 64 * DIM + h * HD + lane;
    #pragma unroll
    for (int rr = 0; rr < 8; rr++)
        ob[(size_t)(i0 + rr) * DIM] = acc[rr];
}

// ---------------- launch ----------------
extern "C" void kernel_launch(void* const* d_in, const int* in_sizes, int n_in,
                              void* d_out, int out_size)
{
    const float* x     = (const float*)d_in[0];
    const float* x2    = (const float*)d_in[1];
    const float* n1w   = (const float*)d_in[2];
    const float* n1b   = (const float*)d_in[3];
    const float* qkvw  = (const float*)d_in[4];
    const float* qkvb  = (const float*)d_in[5];
    const float* qkv2w = (const float*)d_in[6];
    const float* qkv2b = (const float*)d_in[7];
    const float* relb  = (const float*)d_in[8];
    const float* projw = (const float*)d_in[9];
    const float* projb = (const float*)d_in[10];
    const float* n2w   = (const float*)d_in[11];
    const float* n2b   = (const float*)d_in[12];
    const float* fc1w  = (const float*)d_in[13];
    const float* fc1b  = (const float*)d_in[14];
    const float* fc2w  = (const float*)d_in[15];
    const float* fc2b  = (const float*)d_in[16];
    float* out = (float*)d_out;

    float *p_xn, *p_q, *p_kv, *p_ao, *p_x1, *p_ln2, *p_h;
    cudaGetSymbolAddress((void**)&p_xn,  g_xn);
    cudaGetSymbolAddress((void**)&p_q,   g_q);
    cudaGetSymbolAddress((void**)&p_kv,  g_kv);
    cudaGetSymbolAddress((void**)&p_ao,  g_ao);
    cudaGetSymbolAddress((void**)&p_x1,  g_x1);
    cudaGetSymbolAddress((void**)&p_ln2, g_ln2);
    cudaGetSymbolAddress((void**)&p_h,   g_h);

    const int attn_smem = ATTN_SMEM_FLOATS * (int)sizeof(float);
    cudaFuncSetAttribute(attn_kernel, cudaFuncAttributeMaxDynamicSharedMemorySize, attn_smem);

    // 1. LN1 + window partition
    ln_kernel<0><<<NQTOK, 192>>>(x, n1w, n1b, p_xn);
    // 2. q projection (window order)
    gemm_kernel<0, 192, 192><<<dim3(512, 3), 256>>>(p_xn, qkvw, qkvb, p_q, nullptr);
    // 3. kv projection (gather x2 through 16x16 window partition)
    gemm_kernel<1, 384, 192><<<dim3(2048, 6), 256>>>(x2, qkv2w, qkv2b, p_kv, nullptr);
    // 4. windowed cross attention
    attn_kernel<<<dim3(NWIN, HEADS), 256, attn_smem>>>(relb);
    // 5. output projection + shortcut + window reverse -> natural order
    gemm_kernel<2, 192, 192><<<dim3(512, 3), 256>>>(p_ao, projw, projb, p_x1, x);
    // 6. LN2
    ln_kernel<1><<<NQTOK, 192>>>(p_x1, n2w, n2b, p_ln2);
    // 7. fc1 + gelu
    gemm_kernel<3, 768, 192><<<dim3(512, 12), 256>>>(p_ln2, fc1w, fc1b, p_h, nullptr);
    // 8. fc2 + residual -> output
    gemm_kernel<4, 192, 768><<<dim3(512, 3), 256>>>(p_h, fc2w, fc2b, out, p_x1);
}

// round 5
// speedup vs baseline: 1.4867x; 1.4867x over previous
#include <cuda_runtime.h>
#include <math.h>
#include <stdint.h>

#define DIM   192
#define HEADS 6
#define HD    32
#define NWIN  1024          // 4 * 16 * 16
#define NQTOK 65536         // 1024 * 64  (== B*L)
#define NKVTOK 262144       // 1024 * 256
#define SCALE 0.17677669529663687f   // 32^-0.5

// ---------------- scratch (device globals; no runtime allocation) ----------------
__device__ float g_xn [(size_t)NQTOK * DIM];        // LN1 output, window order
__device__ float g_q  [(size_t)NQTOK * DIM];        // q projection, window order
__device__ float g_kv [(size_t)NKVTOK * 2 * DIM];   // k | v, window order
__device__ float g_ao [(size_t)NQTOK * DIM];        // attention output, window order
__device__ float g_x1 [(size_t)NQTOK * DIM];        // x after first residual, natural order
__device__ float g_ln2[(size_t)NQTOK * DIM];        // LN2 output
__device__ float g_h  [(size_t)NQTOK * 4 * DIM];    // gelu(fc1) output

// ---------------- helpers ----------------
__device__ __forceinline__ float to_tf32(float x) {
    uint32_t u;
    asm("cvt.rna.tf32.f32 %0, %1;" : "=r"(u) : "f"(x));
    return __uint_as_float(u);
}

__device__ __forceinline__ void mma_tf32(float* d, const float* a, const float* b) {
    asm volatile(
        "mma.sync.aligned.m16n8k8.row.col.f32.tf32.tf32.f32 "
        "{%0,%1,%2,%3}, {%4,%5,%6,%7}, {%8,%9}, {%0,%1,%2,%3};\n"
        : "+f"(d[0]), "+f"(d[1]), "+f"(d[2]), "+f"(d[3])
        : "r"(__float_as_uint(a[0])), "r"(__float_as_uint(a[1])),
          "r"(__float_as_uint(a[2])), "r"(__float_as_uint(a[3])),
          "r"(__float_as_uint(b[0])), "r"(__float_as_uint(b[1])));
}

// ---------------- LayerNorm (one token per block, 192 threads) ----------------
template<int MODE>
__global__ __launch_bounds__(192) void ln_kernel(
    const float* __restrict__ x, const float* __restrict__ w,
    const float* __restrict__ b, float* __restrict__ out)
{
    int tok = blockIdx.x;
    int tid = threadIdx.x;
    int in_row, out_row;
    if (MODE == 0) {
        int win = tok >> 6, t = tok & 63;
        int bb = win >> 8, wi = win & 255;
        int wr = wi >> 4,  wc = wi & 15;
        int r  = t  >> 3,  c  = t  & 7;
        in_row  = bb * 16384 + (wr * 8 + r) * 128 + (wc * 8 + c);
        out_row = tok;
    } else {
        in_row = out_row = tok;
    }
    float v = x[(size_t)in_row * DIM + tid];
    float s1 = v, s2 = v * v;
    #pragma unroll
    for (int off = 16; off; off >>= 1) {
        s1 += __shfl_xor_sync(0xffffffffu, s1, off);
        s2 += __shfl_xor_sync(0xffffffffu, s2, off);
    }
    __shared__ float red[12];
    int warp = tid >> 5, lane = tid & 31;
    if (lane == 0) { red[warp] = s1; red[6 + warp] = s2; }
    __syncthreads();
    if (tid == 0) {
        float a = 0.f, c2 = 0.f;
        #pragma unroll
        for (int i = 0; i < 6; i++) { a += red[i]; c2 += red[6 + i]; }
        red[0] = a; red[6] = c2;
    }
    __syncthreads();
    float mean = red[0] * (1.0f / 192.0f);
    float var  = red[6] * (1.0f / 192.0f) - mean * mean;
    float rstd = rsqrtf(var + 1e-5f);
    out[(size_t)out_row * DIM + tid] = (v - mean) * rstd * w[tid] + b[tid];
}

// ---------------- TF32 tensor-core GEMM: C = A @ W^T + bias ----------------
// W is (N, K) row-major. 128x64 block tile, BK=32, 8 warps (4m x 2n), warp 32x32.
// MODE 0: plain.  MODE 1: gather A rows through 16x16 window partition of x2.
// MODE 2: + add[nat_row], store window-reversed.  MODE 3: exact gelu.
// MODE 4: + add[row].
template<int MODE, int N, int K>
__global__ __launch_bounds__(256) void gemm_tf32(
    const float* __restrict__ A, const float* __restrict__ W,
    const float* __restrict__ bias, float* __restrict__ C,
    const float* __restrict__ add)
{
    constexpr int BM = 128, BN = 64, BK = 32, AS = BK + 4;   // AS=36
    __shared__ float As[BM * AS];
    __shared__ float Bs[BN * AS];

    int tid = threadIdx.x;
    int mb = blockIdx.x * BM, nb = blockIdx.y * BN;
    int warp = tid >> 5, lane = tid & 31;
    int wm = warp & 3, wn = warp >> 2;         // 4 x 2 warp grid
    int g = lane >> 2, tig = lane & 3;

    int arow = tid >> 3;                       // 0..31
    int acol = (tid & 7) * 4;                  // 0..28

    int asrc[4];
    #pragma unroll
    for (int p = 0; p < 4; p++) {
        int r = mb + arow + p * 32;
        if (MODE == 1) {
            int win = r >> 8, t = r & 255;
            int bb = win >> 8, wi = win & 255;
            int wr = wi >> 4,  wc = wi & 15;
            int rr = t  >> 4,  cc = t  & 15;
            asrc[p] = bb * 65536 + (wr * 16 + rr) * 256 + (wc * 16 + cc);
        } else {
            asrc[p] = r;
        }
    }

    float acc[2][4][4];
    #pragma unroll
    for (int mt = 0; mt < 2; mt++)
        #pragma unroll
        for (int nt = 0; nt < 4; nt++)
            #pragma unroll
            for (int i = 0; i < 4; i++) acc[mt][nt][i] = 0.f;

    for (int k0 = 0; k0 < K; k0 += BK) {
        #pragma unroll
        for (int p = 0; p < 4; p++) {
            float4 v = *(const float4*)(A + (size_t)asrc[p] * K + k0 + acol);
            float* s = &As[(arow + p * 32) * AS + acol];
            s[0] = to_tf32(v.x); s[1] = to_tf32(v.y);
            s[2] = to_tf32(v.z); s[3] = to_tf32(v.w);
        }
        #pragma unroll
        for (int p = 0; p < 2; p++) {
            int r = arow + p * 32;  // 0..63
            float4 v = *(const float4*)(W + (size_t)(nb + r) * K + k0 + acol);
            float* s = &Bs[r * AS + acol];
            s[0] = to_tf32(v.x); s[1] = to_tf32(v.y);
            s[2] = to_tf32(v.z); s[3] = to_tf32(v.w);
        }
        __syncthreads();

        #pragma unroll
        for (int ks = 0; ks < 4; ks++) {
            int kk = ks * 8;
            float a[2][4], b[4][2];
            #pragma unroll
            for (int mt = 0; mt < 2; mt++) {
                int r0 = wm * 32 + mt * 16;
                a[mt][0] = As[(r0 + g) * AS + kk + tig];
                a[mt][1] = As[(r0 + g + 8) * AS + kk + tig];
                a[mt][2] = As[(r0 + g) * AS + kk + tig + 4];
                a[mt][3] = As[(r0 + g + 8) * AS + kk + tig + 4];
            }
            #pragma unroll
            for (int nt = 0; nt < 4; nt++) {
                int c0 = wn * 32 + nt * 8;
                b[nt][0] = Bs[(c0 + g) * AS + kk + tig];
                b[nt][1] = Bs[(c0 + g) * AS + kk + tig + 4];
            }
            #pragma unroll
            for (int mt = 0; mt < 2; mt++)
                #pragma unroll
                for (int nt = 0; nt < 4; nt++)
                    mma_tf32(acc[mt][nt], a[mt], b[nt]);
        }
        __syncthreads();
    }

    // epilogue: c0,c1 -> row (g), cols tig*2, tig*2+1 ; c2,c3 -> row (g+8)
    #pragma unroll
    for (int mt = 0; mt < 2; mt++) {
        #pragma unroll
        for (int half = 0; half < 2; half++) {
            int row = mb + wm * 32 + mt * 16 + g + half * 8;
            int nat = row;
            if (MODE == 2) {
                int win = row >> 6, t = row & 63;
                int bI = win >> 8, wi = win & 255;
                int wr = wi >> 4,  wc = wi & 15;
                int rr = t  >> 3,  cc = t  & 7;
                nat = bI * 16384 + (wr * 8 + rr) * 128 + (wc * 8 + cc);
            }
            #pragma unroll
            for (int nt = 0; nt < 4; nt++) {
                int col = nb + wn * 32 + nt * 8 + tig * 2;
                float2 o;
                o.x = acc[mt][nt][half * 2 + 0] + bias[col];
                o.y = acc[mt][nt][half * 2 + 1] + bias[col + 1];
                if (MODE == 2) {
                    float2 s = *(const float2*)(add + (size_t)nat * DIM + col);
                    o.x += s.x; o.y += s.y;
                    *(float2*)(C + (size_t)nat * DIM + col) = o;
                } else if (MODE == 3) {
                    o.x = 0.5f * o.x * (1.0f + erff(o.x * 0.70710678118654752f));
                    o.y = 0.5f * o.y * (1.0f + erff(o.y * 0.70710678118654752f));
                    *(float2*)(C + (size_t)row * N + col) = o;
                } else if (MODE == 4) {
                    float2 s = *(const float2*)(add + (size_t)row * N + col);
                    o.x += s.x; o.y += s.y;
                    *(float2*)(C + (size_t)row * N + col) = o;
                } else {
                    *(float2*)(C + (size_t)row * N + col) = o;
                }
            }
        }
    }
}

// ---------------- Attention: one block per (window, head), 512 threads ----------
// Warp w owns score rows 4w..4w+3 end-to-end. K loaded once per 32 FMAs (8x reuse
// vs previous version).
#define KT_STRIDE 260
#define ATTN_SMEM_FLOATS (2048 + 32 * KT_STRIDE + 8192 + 16384 + 532)

__global__ __launch_bounds__(512) void attn_kernel(const float* __restrict__ rel_bias)
{
    extern __shared__ float sm[];
    float* sQ  = sm;                      // 64*32   = 2048
    float* sKT = sm + 2048;               // 32*260  = 8320
    float* sV  = sKT + 32 * KT_STRIDE;    // 256*32  = 8192
    float* sS  = sV + 8192;               // 64*256  = 16384
    float* sB  = sS + 16384;              // 529 (+pad)

    int win = blockIdx.x, h = blockIdx.y;
    int tid = threadIdx.x;

    for (int r = tid; r < 529; r += 512) sB[r] = rel_bias[r * HEADS + h];

    const float* qb = g_q + (size_t)win * 64 * DIM + h * HD;
    for (int idx = tid; idx < 64 * 32; idx += 512) {
        int i = idx >> 5, d = idx & 31;
        sQ[idx] = qb[i * DIM + d] * SCALE;
    }
    const float* kb = g_kv + (size_t)win * 256 * (2 * DIM) + h * HD;
    const float* vb = kb + DIM;
    for (int idx = tid; idx < 256 * 32; idx += 512) {
        int j = idx >> 5, d = idx & 31;
        sKT[d * KT_STRIDE + j] = kb[(size_t)j * (2 * DIM) + d];
        sV[idx]                = vb[(size_t)j * (2 * DIM) + d];
    }
    __syncthreads();

    int warp = tid >> 5, lane = tid & 31;
    int i0 = warp * 4;

    // ---- S = (q*scale) @ k^T : warp rows i0..i0+3, lane -> cols lane*8..+7
    float acc[4][8];
    #pragma unroll
    for (int r = 0; r < 4; r++)
        #pragma unroll
        for (int u = 0; u < 8; u++) acc[r][u] = 0.f;

    #pragma unroll 8
    for (int kk = 0; kk < 32; kk++) {
        float4 k0 = *(const float4*)&sKT[kk * KT_STRIDE + lane * 8];
        float4 k1 = *(const float4*)&sKT[kk * KT_STRIDE + lane * 8 + 4];
        #pragma unroll
        for (int r = 0; r < 4; r++) {
            float qv = sQ[(i0 + r) * 32 + kk];
            acc[r][0] += qv * k0.x; acc[r][1] += qv * k0.y;
            acc[r][2] += qv * k0.z; acc[r][3] += qv * k0.w;
            acc[r][4] += qv * k1.x; acc[r][5] += qv * k1.y;
            acc[r][6] += qv * k1.z; acc[r][7] += qv * k1.w;
        }
    }

    // ---- bias add + store to sS
    #pragma unroll
    for (int r = 0; r < 4; r++) {
        int i = i0 + r;
        int r1 = i >> 3, c1 = i & 7;
        float o[8];
        #pragma unroll
        for (int u = 0; u < 8; u++) {
            int j = lane * 8 + u;
            int ridx = (r1 - (j >> 4) + 15) * 23 + (c1 - (j & 15) + 15);
            o[u] = acc[r][u] + sB[ridx];
        }
        *(float4*)&sS[i * 256 + lane * 8]     = *(float4*)&o[0];
        *(float4*)&sS[i * 256 + lane * 8 + 4] = *(float4*)&o[4];
    }
    __syncwarp();

    // ---- row softmax (warp-local rows)
    #pragma unroll
    for (int r = 0; r < 4; r++) {
        int i = i0 + r;
        float* row = sS + i * 256;
        float vals[8];
        float m = -1e30f;
        #pragma unroll
        for (int u = 0; u < 8; u++) { vals[u] = row[lane + u * 32]; m = fmaxf(m, vals[u]); }
        #pragma unroll
        for (int off = 16; off; off >>= 1) m = fmaxf(m, __shfl_xor_sync(0xffffffffu, m, off));
        float s = 0.f;
        #pragma unroll
        for (int u = 0; u < 8; u++) { vals[u] = __expf(vals[u] - m); s += vals[u]; }
        #pragma unroll
        for (int off = 16; off; off >>= 1) s += __shfl_xor_sync(0xffffffffu, s, off);
        float inv = 1.0f / s;
        #pragma unroll
        for (int u = 0; u < 8; u++) row[lane + u * 32] = vals[u] * inv;
    }
    __syncwarp();

    // ---- O = P @ v : warp rows i0..i0+3, lane -> output dim d
    float accO[4] = {0.f, 0.f, 0.f, 0.f};
    #pragma unroll 4
    for (int j4 = 0; j4 < 64; j4++) {
        int j = j4 * 4;
        float v0 = sV[(j + 0) * 32 + lane];
        float v1 = sV[(j + 1) * 32 + lane];
        float v2 = sV[(j + 2) * 32 + lane];
        float v3 = sV[(j + 3) * 32 + lane];
        #pragma unroll
        for (int r = 0; r < 4; r++) {
            float4 p = *(const float4*)&sS[(i0 + r) * 256 + j];
            accO[r] += p.x * v0 + p.y * v1 + p.z * v2 + p.w * v3;
        }
    }
    float* ob = g_ao + (size_t)win * 64 * DIM + h * HD + lane;
    #pragma unroll
    for (int r = 0; r < 4; r++)
        ob[(size_t)(i0 + r) * DIM] = accO[r];
}

// ---------------- launch ----------------
extern "C" void kernel_launch(void* const* d_in, const int* in_sizes, int n_in,
                              void* d_out, int out_size)
{
    const float* x     = (const float*)d_in[0];
    const float* x2    = (const float*)d_in[1];
    const float* n1w   = (const float*)d_in[2];
    const float* n1b   = (const float*)d_in[3];
    const float* qkvw  = (const float*)d_in[4];
    const float* qkvb  = (const float*)d_in[5];
    const float* qkv2w = (const float*)d_in[6];
    const float* qkv2b = (const float*)d_in[7];
    const float* relb  = (const float*)d_in[8];
    const float* projw = (const float*)d_in[9];
    const float* projb = (const float*)d_in[10];
    const float* n2w   = (const float*)d_in[11];
    const float* n2b   = (const float*)d_in[12];
    const float* fc1w  = (const float*)d_in[13];
    const float* fc1b  = (const float*)d_in[14];
    const float* fc2w  = (const float*)d_in[15];
    const float* fc2b  = (const float*)d_in[16];
    float* out = (float*)d_out;

    float *p_xn, *p_q, *p_kv, *p_ao, *p_x1, *p_ln2, *p_h;
    cudaGetSymbolAddress((void**)&p_xn,  g_xn);
    cudaGetSymbolAddress((void**)&p_q,   g_q);
    cudaGetSymbolAddress((void**)&p_kv,  g_kv);
    cudaGetSymbolAddress((void**)&p_ao,  g_ao);
    cudaGetSymbolAddress((void**)&p_x1,  g_x1);
    cudaGetSymbolAddress((void**)&p_ln2, g_ln2);
    cudaGetSymbolAddress((void**)&p_h,   g_h);

    const int attn_smem = ATTN_SMEM_FLOATS * (int)sizeof(float);
    cudaFuncSetAttribute(attn_kernel, cudaFuncAttributeMaxDynamicSharedMemorySize, attn_smem);

    // 1. LN1 + window partition
    ln_kernel<0><<<NQTOK, 192>>>(x, n1w, n1b, p_xn);
    // 2. q projection (window order)
    gemm_tf32<0, 192, 192><<<dim3(512, 3), 256>>>(p_xn, qkvw, qkvb, p_q, nullptr);
    // 3. kv projection (gather x2 through 16x16 window partition)
    gemm_tf32<1, 384, 192><<<dim3(2048, 6), 256>>>(x2, qkv2w, qkv2b, p_kv, nullptr);
    // 4. windowed cross attention
    attn_kernel<<<dim3(NWIN, HEADS), 512, attn_smem>>>(relb);
    // 5. output projection + shortcut + window reverse -> natural order
    gemm_tf32<2, 192, 192><<<dim3(512, 3), 256>>>(p_ao, projw, projb, p_x1, x);
    // 6. LN2
    ln_kernel<1><<<NQTOK, 192>>>(p_x1, n2w, n2b, p_ln2);
    // 7. fc1 + gelu
    gemm_tf32<3, 768, 192><<<dim3(512, 12), 256>>>(p_ln2, fc1w, fc1b, p_h, nullptr);
    // 8. fc2 + residual -> output
    gemm_tf32<4, 192, 768><<<dim3(512, 3), 256>>>(p_h, fc2w, fc2b, out, p_x1);
}

// round 6
// speedup vs baseline: 1.7908x; 1.2045x over previous
#include <cuda_runtime.h>
#include <math.h>
#include <stdint.h>

#define DIM   192
#define HEADS 6
#define HD    32
#define NWIN  1024          // 4 * 16 * 16
#define NQTOK 65536         // 1024 * 64  (== B*L)
#define NKVTOK 262144       // 1024 * 256
#define SCALE 0.17677669529663687f   // 32^-0.5

// ---------------- scratch (device globals; no runtime allocation) ----------------
__device__ float g_xn [(size_t)NQTOK * DIM];        // LN1 output, window order
__device__ float g_q  [(size_t)NQTOK * DIM];        // q projection, window order
__device__ float g_kv [(size_t)NKVTOK * 2 * DIM];   // k | v, window order
__device__ float g_ao [(size_t)NQTOK * DIM];        // attention output, window order
__device__ float g_x1 [(size_t)NQTOK * DIM];        // x after first residual, natural order
__device__ float g_ln2[(size_t)NQTOK * DIM];        // LN2 output
__device__ float g_h  [(size_t)NQTOK * 4 * DIM];    // gelu(fc1) output

// ---------------- helpers ----------------
__device__ __forceinline__ float to_tf32(float x) {
    uint32_t u;
    asm("cvt.rna.tf32.f32 %0, %1;" : "=r"(u) : "f"(x));
    return __uint_as_float(u);
}

__device__ __forceinline__ void mma_tf32(float* d, const float* a, const float* b) {
    asm volatile(
        "mma.sync.aligned.m16n8k8.row.col.f32.tf32.tf32.f32 "
        "{%0,%1,%2,%3}, {%4,%5,%6,%7}, {%8,%9}, {%0,%1,%2,%3};\n"
        : "+f"(d[0]), "+f"(d[1]), "+f"(d[2]), "+f"(d[3])
        : "r"(__float_as_uint(a[0])), "r"(__float_as_uint(a[1])),
          "r"(__float_as_uint(a[2])), "r"(__float_as_uint(a[3])),
          "r"(__float_as_uint(b[0])), "r"(__float_as_uint(b[1])));
}

// ---------------- LayerNorm (one token per block, 192 threads) ----------------
template<int MODE>
__global__ __launch_bounds__(192) void ln_kernel(
    const float* __restrict__ x, const float* __restrict__ w,
    const float* __restrict__ b, float* __restrict__ out)
{
    int tok = blockIdx.x;
    int tid = threadIdx.x;
    int in_row, out_row;
    if (MODE == 0) {
        int win = tok >> 6, t = tok & 63;
        int bb = win >> 8, wi = win & 255;
        int wr = wi >> 4,  wc = wi & 15;
        int r  = t  >> 3,  c  = t  & 7;
        in_row  = bb * 16384 + (wr * 8 + r) * 128 + (wc * 8 + c);
        out_row = tok;
    } else {
        in_row = out_row = tok;
    }
    float v = x[(size_t)in_row * DIM + tid];
    float s1 = v, s2 = v * v;
    #pragma unroll
    for (int off = 16; off; off >>= 1) {
        s1 += __shfl_xor_sync(0xffffffffu, s1, off);
        s2 += __shfl_xor_sync(0xffffffffu, s2, off);
    }
    __shared__ float red[12];
    int warp = tid >> 5, lane = tid & 31;
    if (lane == 0) { red[warp] = s1; red[6 + warp] = s2; }
    __syncthreads();
    if (tid == 0) {
        float a = 0.f, c2 = 0.f;
        #pragma unroll
        for (int i = 0; i < 6; i++) { a += red[i]; c2 += red[6 + i]; }
        red[0] = a; red[6] = c2;
    }
    __syncthreads();
    float mean = red[0] * (1.0f / 192.0f);
    float var  = red[6] * (1.0f / 192.0f) - mean * mean;
    float rstd = rsqrtf(var + 1e-5f);
    out[(size_t)out_row * DIM + tid] = (v - mean) * rstd * w[tid] + b[tid];
}

// ---------------- TF32 tensor-core GEMM: C = A @ W^T + bias ----------------
template<int MODE, int N, int K>
__global__ __launch_bounds__(256) void gemm_tf32(
    const float* __restrict__ A, const float* __restrict__ W,
    const float* __restrict__ bias, float* __restrict__ C,
    const float* __restrict__ add)
{
    constexpr int BM = 128, BN = 64, BK = 32, AS = BK + 4;   // AS=36
    __shared__ float As[BM * AS];
    __shared__ float Bs[BN * AS];

    int tid = threadIdx.x;
    int mb = blockIdx.x * BM, nb = blockIdx.y * BN;
    int warp = tid >> 5, lane = tid & 31;
    int wm = warp & 3, wn = warp >> 2;         // 4 x 2 warp grid
    int g = lane >> 2, tig = lane & 3;

    int arow = tid >> 3;                       // 0..31
    int acol = (tid & 7) * 4;                  // 0..28

    int asrc[4];
    #pragma unroll
    for (int p = 0; p < 4; p++) {
        int r = mb + arow + p * 32;
        if (MODE == 1) {
            int win = r >> 8, t = r & 255;
            int bb = win >> 8, wi = win & 255;
            int wr = wi >> 4,  wc = wi & 15;
            int rr = t  >> 4,  cc = t  & 15;
            asrc[p] = bb * 65536 + (wr * 16 + rr) * 256 + (wc * 16 + cc);
        } else {
            asrc[p] = r;
        }
    }

    float acc[2][4][4];
    #pragma unroll
    for (int mt = 0; mt < 2; mt++)
        #pragma unroll
        for (int nt = 0; nt < 4; nt++)
            #pragma unroll
            for (int i = 0; i < 4; i++) acc[mt][nt][i] = 0.f;

    for (int k0 = 0; k0 < K; k0 += BK) {
        #pragma unroll
        for (int p = 0; p < 4; p++) {
            float4 v = *(const float4*)(A + (size_t)asrc[p] * K + k0 + acol);
            float* s = &As[(arow + p * 32) * AS + acol];
            s[0] = to_tf32(v.x); s[1] = to_tf32(v.y);
            s[2] = to_tf32(v.z); s[3] = to_tf32(v.w);
        }
        #pragma unroll
        for (int p = 0; p < 2; p++) {
            int r = arow + p * 32;  // 0..63
            float4 v = *(const float4*)(W + (size_t)(nb + r) * K + k0 + acol);
            float* s = &Bs[r * AS + acol];
            s[0] = to_tf32(v.x); s[1] = to_tf32(v.y);
            s[2] = to_tf32(v.z); s[3] = to_tf32(v.w);
        }
        __syncthreads();

        #pragma unroll
        for (int ks = 0; ks < 4; ks++) {
            int kk = ks * 8;
            float a[2][4], b[4][2];
            #pragma unroll
            for (int mt = 0; mt < 2; mt++) {
                int r0 = wm * 32 + mt * 16;
                a[mt][0] = As[(r0 + g) * AS + kk + tig];
                a[mt][1] = As[(r0 + g + 8) * AS + kk + tig];
                a[mt][2] = As[(r0 + g) * AS + kk + tig + 4];
                a[mt][3] = As[(r0 + g + 8) * AS + kk + tig + 4];
            }
            #pragma unroll
            for (int nt = 0; nt < 4; nt++) {
                int c0 = wn * 32 + nt * 8;
                b[nt][0] = Bs[(c0 + g) * AS + kk + tig];
                b[nt][1] = Bs[(c0 + g) * AS + kk + tig + 4];
            }
            #pragma unroll
            for (int mt = 0; mt < 2; mt++)
                #pragma unroll
                for (int nt = 0; nt < 4; nt++)
                    mma_tf32(acc[mt][nt], a[mt], b[nt]);
        }
        __syncthreads();
    }

    #pragma unroll
    for (int mt = 0; mt < 2; mt++) {
        #pragma unroll
        for (int half = 0; half < 2; half++) {
            int row = mb + wm * 32 + mt * 16 + g + half * 8;
            int nat = row;
            if (MODE == 2) {
                int win = row >> 6, t = row & 63;
                int bI = win >> 8, wi = win & 255;
                int wr = wi >> 4,  wc = wi & 15;
                int rr = t  >> 3,  cc = t  & 7;
                nat = bI * 16384 + (wr * 8 + rr) * 128 + (wc * 8 + cc);
            }
            #pragma unroll
            for (int nt = 0; nt < 4; nt++) {
                int col = nb + wn * 32 + nt * 8 + tig * 2;
                float2 o;
                o.x = acc[mt][nt][half * 2 + 0] + bias[col];
                o.y = acc[mt][nt][half * 2 + 1] + bias[col + 1];
                if (MODE == 2) {
                    float2 s = *(const float2*)(add + (size_t)nat * DIM + col);
                    o.x += s.x; o.y += s.y;
                    *(float2*)(C + (size_t)nat * DIM + col) = o;
                } else if (MODE == 3) {
                    o.x = 0.5f * o.x * (1.0f + erff(o.x * 0.70710678118654752f));
                    o.y = 0.5f * o.y * (1.0f + erff(o.y * 0.70710678118654752f));
                    *(float2*)(C + (size_t)row * N + col) = o;
                } else if (MODE == 4) {
                    float2 s = *(const float2*)(add + (size_t)row * N + col);
                    o.x += s.x; o.y += s.y;
                    *(float2*)(C + (size_t)row * N + col) = o;
                } else {
                    *(float2*)(C + (size_t)row * N + col) = o;
                }
            }
        }
    }
}

// ---------------- Attention (tensor cores): one block per (window, head) -------
// 512 threads = 16 warps.
// Phase 1 (QK):  warp w = (mi = w&3, nj = w>>2): S tile rows mi*16.., cols nj*64..
// Phase 2: softmax in registers (quad shuffles + 64x4 smem cross-warp reduce)
// Phase 3 (PV):  warp w = (mi = w&3, kj = w>>2): K-slice kj*64, reduce via smem.
#define QS 36      // sQ/sK row stride
#define PS 260     // sS / sVT row stride (bank = 4g+tig, conflict-free frags)
#define OFF_Q  0
#define OFF_K  2304
#define OFF_VT 11520
#define OFF_S  19840
#define OFF_B  36480
#define OFF_R1 37012
#define OFF_R2 37268
#define ATTN_SMEM_FLOATS 37524
#define PART_STRIDE 33     // partial buffer overlays sQ/sK: 4*64*33 = 8448 floats

__global__ __launch_bounds__(512) void attn_kernel(const float* __restrict__ rel_bias)
{
    extern __shared__ float sm[];
    float* sQ  = sm + OFF_Q;    // 64 x 36 (tf32, pre-scaled)
    float* sK  = sm + OFF_K;    // 256 x 36 (tf32)
    float* sVT = sm + OFF_VT;   // 32 x 260 (tf32, transposed V)
    float* sS  = sm + OFF_S;    // 64 x 260 (P, tf32)
    float* sB  = sm + OFF_B;    // 529
    float* sR1 = sm + OFF_R1;   // 64 x 4 row-max partials
    float* sR2 = sm + OFF_R2;   // 64 x 4 row-sum partials
    float* sPart = sm;          // PV partials overlay: [4][64][33]

    int win = blockIdx.x, h = blockIdx.y;
    int tid = threadIdx.x;

    for (int r = tid; r < 529; r += 512) sB[r] = rel_bias[r * HEADS + h];

    const float* qb = g_q + (size_t)win * 64 * DIM + h * HD;
    for (int idx = tid; idx < 64 * 32; idx += 512) {
        int i = idx >> 5, d = idx & 31;
        sQ[i * QS + d] = to_tf32(qb[i * DIM + d] * SCALE);
    }
    const float* kb = g_kv + (size_t)win * 256 * (2 * DIM) + h * HD;
    const float* vb = kb + DIM;
    for (int idx = tid; idx < 256 * 32; idx += 512) {
        int j = idx >> 5, d = idx & 31;
        sK[j * QS + d]  = to_tf32(kb[(size_t)j * (2 * DIM) + d]);
        sVT[d * PS + j] = to_tf32(vb[(size_t)j * (2 * DIM) + d]);
    }
    __syncthreads();

    int warp = tid >> 5, lane = tid & 31;
    int g = lane >> 2, tig = lane & 3;
    int mi = warp & 3, nj = warp >> 2;

    // ---- Phase 1: S = Q @ K^T  (acc[nt][4], nt = 8 subtiles of 8 cols)
    float acc[8][4];
    #pragma unroll
    for (int nt = 0; nt < 8; nt++)
        #pragma unroll
        for (int i = 0; i < 4; i++) acc[nt][i] = 0.f;

    int r0 = mi * 16;
    #pragma unroll
    for (int ks = 0; ks < 4; ks++) {
        int kk = ks * 8;
        float a[4];
        a[0] = sQ[(r0 + g) * QS + kk + tig];
        a[1] = sQ[(r0 + g + 8) * QS + kk + tig];
        a[2] = sQ[(r0 + g) * QS + kk + tig + 4];
        a[3] = sQ[(r0 + g + 8) * QS + kk + tig + 4];
        #pragma unroll
        for (int nt = 0; nt < 8; nt++) {
            int c0 = nj * 64 + nt * 8;
            float b[2];
            b[0] = sK[(c0 + g) * QS + kk + tig];
            b[1] = sK[(c0 + g) * QS + kk + tig + 4];
            mma_tf32(acc[nt], a, b);
        }
    }

    // ---- bias add
    int i_lo = r0 + g, i_hi = i_lo + 8;
    int r1lo = i_lo >> 3, c1lo = i_lo & 7;
    int r1hi = i_hi >> 3, c1hi = i_hi & 7;
    #pragma unroll
    for (int nt = 0; nt < 8; nt++) {
        int j0 = nj * 64 + nt * 8 + tig * 2;
        int j1 = j0 + 1;
        acc[nt][0] += sB[(r1lo - (j0 >> 4) + 15) * 23 + (c1lo - (j0 & 15) + 15)];
        acc[nt][1] += sB[(r1lo - (j1 >> 4) + 15) * 23 + (c1lo - (j1 & 15) + 15)];
        acc[nt][2] += sB[(r1hi - (j0 >> 4) + 15) * 23 + (c1hi - (j0 & 15) + 15)];
        acc[nt][3] += sB[(r1hi - (j1 >> 4) + 15) * 23 + (c1hi - (j1 & 15) + 15)];
    }

    // ---- Phase 2: softmax in registers
    float mlo = -1e30f, mhi = -1e30f;
    #pragma unroll
    for (int nt = 0; nt < 8; nt++) {
        mlo = fmaxf(mlo, fmaxf(acc[nt][0], acc[nt][1]));
        mhi = fmaxf(mhi, fmaxf(acc[nt][2], acc[nt][3]));
    }
    #pragma unroll
    for (int off = 1; off < 4; off <<= 1) {
        mlo = fmaxf(mlo, __shfl_xor_sync(0xffffffffu, mlo, off));
        mhi = fmaxf(mhi, __shfl_xor_sync(0xffffffffu, mhi, off));
    }
    if (tig == 0) { sR1[i_lo * 4 + nj] = mlo; sR1[i_hi * 4 + nj] = mhi; }
    __syncthreads();
    mlo = fmaxf(fmaxf(sR1[i_lo * 4 + 0], sR1[i_lo * 4 + 1]),
                fmaxf(sR1[i_lo * 4 + 2], sR1[i_lo * 4 + 3]));
    mhi = fmaxf(fmaxf(sR1[i_hi * 4 + 0], sR1[i_hi * 4 + 1]),
                fmaxf(sR1[i_hi * 4 + 2], sR1[i_hi * 4 + 3]));

    float slo = 0.f, shi = 0.f;
    #pragma unroll
    for (int nt = 0; nt < 8; nt++) {
        acc[nt][0] = __expf(acc[nt][0] - mlo); slo += acc[nt][0];
        acc[nt][1] = __expf(acc[nt][1] - mlo); slo += acc[nt][1];
        acc[nt][2] = __expf(acc[nt][2] - mhi); shi += acc[nt][2];
        acc[nt][3] = __expf(acc[nt][3] - mhi); shi += acc[nt][3];
    }
    #pragma unroll
    for (int off = 1; off < 4; off <<= 1) {
        slo += __shfl_xor_sync(0xffffffffu, slo, off);
        shi += __shfl_xor_sync(0xffffffffu, shi, off);
    }
    if (tig == 0) { sR2[i_lo * 4 + nj] = slo; sR2[i_hi * 4 + nj] = shi; }
    __syncthreads();
    float invlo = 1.0f / (sR2[i_lo * 4 + 0] + sR2[i_lo * 4 + 1] +
                          sR2[i_lo * 4 + 2] + sR2[i_lo * 4 + 3]);
    float invhi = 1.0f / (sR2[i_hi * 4 + 0] + sR2[i_hi * 4 + 1] +
                          sR2[i_hi * 4 + 2] + sR2[i_hi * 4 + 3]);

    // ---- write P (tf32) to sS
    #pragma unroll
    for (int nt = 0; nt < 8; nt++) {
        int j0 = nj * 64 + nt * 8 + tig * 2;
        float2 plo, phi;
        plo.x = to_tf32(acc[nt][0] * invlo); plo.y = to_tf32(acc[nt][1] * invlo);
        phi.x = to_tf32(acc[nt][2] * invhi); phi.y = to_tf32(acc[nt][3] * invhi);
        *(float2*)&sS[i_lo * PS + j0] = plo;
        *(float2*)&sS[i_hi * PS + j0] = phi;
    }
    __syncthreads();

    // ---- Phase 3: O = P @ V  (warp = (mi, kj), K-slice of 64)
    int kj = warp >> 2;
    float accO[4][4];
    #pragma unroll
    for (int nt = 0; nt < 4; nt++)
        #pragma unroll
        for (int i = 0; i < 4; i++) accO[nt][i] = 0.f;

    #pragma unroll
    for (int ks = 0; ks < 8; ks++) {
        int kk = kj * 64 + ks * 8;
        float a[4];
        a[0] = sS[(r0 + g) * PS + kk + tig];
        a[1] = sS[(r0 + g + 8) * PS + kk + tig];
        a[2] = sS[(r0 + g) * PS + kk + tig + 4];
        a[3] = sS[(r0 + g + 8) * PS + kk + tig + 4];
        #pragma unroll
        for (int nt = 0; nt < 4; nt++) {
            float b[2];
            b[0] = sVT[(nt * 8 + g) * PS + kk + tig];
            b[1] = sVT[(nt * 8 + g) * PS + kk + tig + 4];
            mma_tf32(accO[nt], a, b);
        }
    }

    // partials -> smem (overlays sQ/sK; all reads of those finished pre-P-sync)
    #pragma unroll
    for (int nt = 0; nt < 4; nt++) {
        int c0 = nt * 8 + tig * 2;
        float* plo = &sPart[kj * 64 * PART_STRIDE + i_lo * PART_STRIDE + c0];
        float* phi = &sPart[kj * 64 * PART_STRIDE + i_hi * PART_STRIDE + c0];
        plo[0] = accO[nt][0]; plo[1] = accO[nt][1];
        phi[0] = accO[nt][2]; phi[1] = accO[nt][3];
    }
    __syncthreads();

    // reduce 4 K-slices and store
    float* ob = g_ao + (size_t)win * 64 * DIM + h * HD;
    for (int e = tid; e < 2048; e += 512) {
        int row = e >> 5, col = e & 31;
        float s = sPart[0 * 64 * PART_STRIDE + row * PART_STRIDE + col]
                + sPart[1 * 64 * PART_STRIDE + row * PART_STRIDE + col]
                + sPart[2 * 64 * PART_STRIDE + row * PART_STRIDE + col]
                + sPart[3 * 64 * PART_STRIDE + row * PART_STRIDE + col];
        ob[(size_t)row * DIM + col] = s;
    }
}

// ---------------- launch ----------------
extern "C" void kernel_launch(void* const* d_in, const int* in_sizes, int n_in,
                              void* d_out, int out_size)
{
    const float* x     = (const float*)d_in[0];
    const float* x2    = (const float*)d_in[1];
    const float* n1w   = (const float*)d_in[2];
    const float* n1b   = (const float*)d_in[3];
    const float* qkvw  = (const float*)d_in[4];
    const float* qkvb  = (const float*)d_in[5];
    const float* qkv2w = (const float*)d_in[6];
    const float* qkv2b = (const float*)d_in[7];
    const float* relb  = (const float*)d_in[8];
    const float* projw = (const float*)d_in[9];
    const float* projb = (const float*)d_in[10];
    const float* n2w   = (const float*)d_in[11];
    const float* n2b   = (const float*)d_in[12];
    const float* fc1w  = (const float*)d_in[13];
    const float* fc1b  = (const float*)d_in[14];
    const float* fc2w  = (const float*)d_in[15];
    const float* fc2b  = (const float*)d_in[16];
    float* out = (float*)d_out;

    float *p_xn, *p_q, *p_kv, *p_ao, *p_x1, *p_ln2, *p_h;
    cudaGetSymbolAddress((void**)&p_xn,  g_xn);
    cudaGetSymbolAddress((void**)&p_q,   g_q);
    cudaGetSymbolAddress((void**)&p_kv,  g_kv);
    cudaGetSymbolAddress((void**)&p_ao,  g_ao);
    cudaGetSymbolAddress((void**)&p_x1,  g_x1);
    cudaGetSymbolAddress((void**)&p_ln2, g_ln2);
    cudaGetSymbolAddress((void**)&p_h,   g_h);

    const int attn_smem = ATTN_SMEM_FLOATS * (int)sizeof(float);
    cudaFuncSetAttribute(attn_kernel, cudaFuncAttributeMaxDynamicSharedMemorySize, attn_smem);

    // 1. LN1 + window partition
    ln_kernel<0><<<NQTOK, 192>>>(x, n1w, n1b, p_xn);
    // 2. q projection (window order)
    gemm_tf32<0, 192, 192><<<dim3(512, 3), 256>>>(p_xn, qkvw, qkvb, p_q, nullptr);
    // 3. kv projection (gather x2 through 16x16 window partition)
    gemm_tf32<1, 384, 192><<<dim3(2048, 6), 256>>>(x2, qkv2w, qkv2b, p_kv, nullptr);
    // 4. windowed cross attention (tensor cores)
    attn_kernel<<<dim3(NWIN, HEADS), 512, attn_smem>>>(relb);
    // 5. output projection + shortcut + window reverse -> natural order
    gemm_tf32<2, 192, 192><<<dim3(512, 3), 256>>>(p_ao, projw, projb, p_x1, x);
    // 6. LN2
    ln_kernel<1><<<NQTOK, 192>>>(p_x1, n2w, n2b, p_ln2);
    // 7. fc1 + gelu
    gemm_tf32<3, 768, 192><<<dim3(512, 12), 256>>>(p_ln2, fc1w, fc1b, p_h, nullptr);
    // 8. fc2 + residual -> output
    gemm_tf32<4, 192, 768><<<dim3(512, 3), 256>>>(p_h, fc2w, fc2b, out, p_x1);
}

// round 7
// speedup vs baseline: 3.0379x; 1.6964x over previous
#include <cuda_runtime.h>
#include <math.h>
#include <stdint.h>

#define DIM   192
#define HEADS 6
#define HD    32
#define NWIN  1024          // 4 * 16 * 16
#define NQTOK 65536         // 1024 * 64  (== B*L)
#define NKVTOK 262144       // 1024 * 256
#define SCALE 0.17677669529663687f   // 32^-0.5

// ---------------- scratch (device globals; no runtime allocation) ----------------
__device__ float g_xn [(size_t)NQTOK * DIM];        // LN1 output, window order
__device__ float g_q  [(size_t)NQTOK * DIM];        // q projection, window order
__device__ float g_kv [(size_t)NKVTOK * 2 * DIM];   // k | v, window order
__device__ float g_ao [(size_t)NQTOK * DIM];        // attention output, window order
__device__ float g_x1 [(size_t)NQTOK * DIM];        // x after first residual
__device__ float g_ln2[(size_t)NQTOK * DIM];        // LN2 output
__device__ float g_h  [(size_t)NQTOK * 4 * DIM];    // gelu(fc1) output

// ---------------- helpers ----------------
__device__ __forceinline__ void mma_tf32(float* d, const float* a, const float* b) {
    asm volatile(
        "mma.sync.aligned.m16n8k8.row.col.f32.tf32.tf32.f32 "
        "{%0,%1,%2,%3}, {%4,%5,%6,%7}, {%8,%9}, {%0,%1,%2,%3};\n"
        : "+f"(d[0]), "+f"(d[1]), "+f"(d[2]), "+f"(d[3])
        : "r"(__float_as_uint(a[0])), "r"(__float_as_uint(a[1])),
          "r"(__float_as_uint(a[2])), "r"(__float_as_uint(a[3])),
          "r"(__float_as_uint(b[0])), "r"(__float_as_uint(b[1])));
}

__device__ __forceinline__ void cp16(uint32_t dst, const void* src) {
    asm volatile("cp.async.cg.shared.global [%0], [%1], 16;\n" :: "r"(dst), "l"(src));
}
#define CP_COMMIT() asm volatile("cp.async.commit_group;\n")
#define CP_WAIT1()  asm volatile("cp.async.wait_group 1;\n")
#define CP_WAIT0()  asm volatile("cp.async.wait_group 0;\n")

// ---------------- LayerNorm (one token per block, 192 threads) ----------------
template<int MODE>
__global__ __launch_bounds__(192) void ln_kernel(
    const float* __restrict__ x, const float* __restrict__ w,
    const float* __restrict__ b, float* __restrict__ out)
{
    int tok = blockIdx.x;
    int tid = threadIdx.x;
    int in_row, out_row;
    if (MODE == 0) {
        int win = tok >> 6, t = tok & 63;
        int bb = win >> 8, wi = win & 255;
        int wr = wi >> 4,  wc = wi & 15;
        int r  = t  >> 3,  c  = t  & 7;
        in_row  = bb * 16384 + (wr * 8 + r) * 128 + (wc * 8 + c);
        out_row = tok;
    } else {
        in_row = out_row = tok;
    }
    float v = x[(size_t)in_row * DIM + tid];
    float s1 = v, s2 = v * v;
    #pragma unroll
    for (int off = 16; off; off >>= 1) {
        s1 += __shfl_xor_sync(0xffffffffu, s1, off);
        s2 += __shfl_xor_sync(0xffffffffu, s2, off);
    }
    __shared__ float red[12];
    int warp = tid >> 5, lane = tid & 31;
    if (lane == 0) { red[warp] = s1; red[6 + warp] = s2; }
    __syncthreads();
    if (tid == 0) {
        float a = 0.f, c2 = 0.f;
        #pragma unroll
        for (int i = 0; i < 6; i++) { a += red[i]; c2 += red[6 + i]; }
        red[0] = a; red[6] = c2;
    }
    __syncthreads();
    float mean = red[0] * (1.0f / 192.0f);
    float var  = red[6] * (1.0f / 192.0f) - mean * mean;
    float rstd = rsqrtf(var + 1e-5f);
    out[(size_t)out_row * DIM + tid] = (v - mean) * rstd * w[tid] + b[tid];
}

// ---------------- TF32 tensor-core GEMM, cp.async double-buffered ----------------
// C = A @ W^T + bias.  W is (N, K) row-major.
// MODE 0: plain.  MODE 1: gather A rows through 16x16 window partition of x2.
// MODE 2: + add[nat_row], store window-reversed.  MODE 3: exact gelu.
// MODE 4: + add[row].
template<int MODE, int N, int K>
__global__ __launch_bounds__(256) void gemm_tf32(
    const float* __restrict__ A, const float* __restrict__ W,
    const float* __restrict__ bias, float* __restrict__ C,
    const float* __restrict__ add)
{
    constexpr int BM = 128, BN = 64, BK = 32, AS = BK + 4;   // AS=36
    constexpr int ASZ = BM * AS, BSZ = BN * AS;
    constexpr int NIT = K / BK;
    __shared__ float As[2][ASZ];
    __shared__ float Bs[2][BSZ];

    int tid = threadIdx.x;
    int mb = blockIdx.x * BM, nb = blockIdx.y * BN;
    int warp = tid >> 5, lane = tid & 31;
    int wm = warp & 3, wn = warp >> 2;         // 4 x 2 warp grid
    int g = lane >> 2, tig = lane & 3;

    int arow = tid >> 3;                       // 0..31
    int acol = (tid & 7) * 4;                  // 0..28

    int asrc[4];
    #pragma unroll
    for (int p = 0; p < 4; p++) {
        int r = mb + arow + p * 32;
        if (MODE == 1) {
            int win = r >> 8, t = r & 255;
            int bb = win >> 8, wi = win & 255;
            int wr = wi >> 4,  wc = wi & 15;
            int rr = t  >> 4,  cc = t  & 15;
            asrc[p] = bb * 65536 + (wr * 16 + rr) * 256 + (wc * 16 + cc);
        } else {
            asrc[p] = r;
        }
    }

    uint32_t sA = (uint32_t)__cvta_generic_to_shared(&As[0][0]);
    uint32_t sB = (uint32_t)__cvta_generic_to_shared(&Bs[0][0]);

    auto issue = [&](int it, int buf) {
        int k0 = it * BK;
        uint32_t da = sA + (uint32_t)(buf * ASZ) * 4u;
        uint32_t db = sB + (uint32_t)(buf * BSZ) * 4u;
        #pragma unroll
        for (int p = 0; p < 4; p++)
            cp16(da + (uint32_t)((arow + p * 32) * AS + acol) * 4u,
                 A + (size_t)asrc[p] * K + k0 + acol);
        #pragma unroll
        for (int p = 0; p < 2; p++) {
            int r = arow + p * 32;
            cp16(db + (uint32_t)(r * AS + acol) * 4u,
                 W + (size_t)(nb + r) * K + k0 + acol);
        }
    };

    float acc[2][4][4];
    #pragma unroll
    for (int mt = 0; mt < 2; mt++)
        #pragma unroll
        for (int nt = 0; nt < 4; nt++)
            #pragma unroll
            for (int i = 0; i < 4; i++) acc[mt][nt][i] = 0.f;

    issue(0, 0); CP_COMMIT();

    for (int it = 0; it < NIT; it++) {
        int buf = it & 1;
        if (it + 1 < NIT) { issue(it + 1, buf ^ 1); CP_COMMIT(); CP_WAIT1(); }
        else             { CP_WAIT0(); }
        __syncthreads();

        const float* as = As[buf];
        const float* bs = Bs[buf];
        #pragma unroll
        for (int ks = 0; ks < 4; ks++) {
            int kk = ks * 8;
            float a[2][4], b[4][2];
            #pragma unroll
            for (int mt = 0; mt < 2; mt++) {
                int r0 = wm * 32 + mt * 16;
                a[mt][0] = as[(r0 + g) * AS + kk + tig];
                a[mt][1] = as[(r0 + g + 8) * AS + kk + tig];
                a[mt][2] = as[(r0 + g) * AS + kk + tig + 4];
                a[mt][3] = as[(r0 + g + 8) * AS + kk + tig + 4];
            }
            #pragma unroll
            for (int nt = 0; nt < 4; nt++) {
                int c0 = wn * 32 + nt * 8;
                b[nt][0] = bs[(c0 + g) * AS + kk + tig];
                b[nt][1] = bs[(c0 + g) * AS + kk + tig + 4];
            }
            #pragma unroll
            for (int mt = 0; mt < 2; mt++)
                #pragma unroll
                for (int nt = 0; nt < 4; nt++)
                    mma_tf32(acc[mt][nt], a[mt], b[nt]);
        }
        __syncthreads();
    }

    #pragma unroll
    for (int mt = 0; mt < 2; mt++) {
        #pragma unroll
        for (int half = 0; half < 2; half++) {
            int row = mb + wm * 32 + mt * 16 + g + half * 8;
            int nat = row;
            if (MODE == 2) {
                int win = row >> 6, t = row & 63;
                int bI = win >> 8, wi = win & 255;
                int wr = wi >> 4,  wc = wi & 15;
                int rr = t  >> 3,  cc = t  & 7;
                nat = bI * 16384 + (wr * 8 + rr) * 128 + (wc * 8 + cc);
            }
            #pragma unroll
            for (int nt = 0; nt < 4; nt++) {
                int col = nb + wn * 32 + nt * 8 + tig * 2;
                float2 o;
                o.x = acc[mt][nt][half * 2 + 0] + bias[col];
                o.y = acc[mt][nt][half * 2 + 1] + bias[col + 1];
                if (MODE == 2) {
                    float2 s = *(const float2*)(add + (size_t)nat * DIM + col);
                    o.x += s.x; o.y += s.y;
                    *(float2*)(C + (size_t)nat * DIM + col) = o;
                } else if (MODE == 3) {
                    o.x = 0.5f * o.x * (1.0f + erff(o.x * 0.70710678118654752f));
                    o.y = 0.5f * o.y * (1.0f + erff(o.y * 0.70710678118654752f));
                    *(float2*)(C + (size_t)row * N + col) = o;
                } else if (MODE == 4) {
                    float2 s = *(const float2*)(add + (size_t)row * N + col);
                    o.x += s.x; o.y += s.y;
                    *(float2*)(C + (size_t)row * N + col) = o;
                } else {
                    *(float2*)(C + (size_t)row * N + col) = o;
                }
            }
        }
    }
}

// ---------------- Attention v2: warp-autonomous, register-resident S -----------
// 128 threads = 4 warps per (window, head). Warp w owns q-rows 16w..16w+15 and
// ALL 256 KV columns: S tile (16x256) lives in MMA accumulators (32 chunks x 4),
// softmax is quad-shuffle only, P -> A-fragments via in-quad shuffle transpose,
// PV accumulated directly. One __syncthreads in the whole kernel.
#define QS 36      // sQ/sK row stride
#define PS 260     // sVT row stride
#define OFF_K  2304
#define OFF_VT 11520
#define OFF_B  19840
#define ATTN_SMEM_FLOATS 20372

__global__ __launch_bounds__(128) void attn_kernel(const float* __restrict__ rel_bias)
{
    extern __shared__ float sm[];
    float* sQ  = sm;             // 64 x 36
    float* sK  = sm + OFF_K;     // 256 x 36
    float* sVT = sm + OFF_VT;    // 32 x 260  (VT[d][j])
    float* sB  = sm + OFF_B;     // 529

    int win = blockIdx.x, h = blockIdx.y;
    int tid = threadIdx.x;

    for (int r = tid; r < 529; r += 128) sB[r] = rel_bias[r * HEADS + h];

    // Q: 64 rows x 32 (float4), plain copy (scale folded into bias-add FMA)
    const float* qb = g_q + (size_t)win * 64 * DIM + h * HD;
    #pragma unroll
    for (int it = 0; it < 4; it++) {
        int idx = tid + it * 128;          // 0..511
        int i = idx >> 3, qd = (idx & 7) * 4;
        float4 v = *(const float4*)(qb + (size_t)i * DIM + qd);
        *(float4*)&sQ[i * QS + qd] = v;
    }
    // K, V: 256 rows x 32 each
    const float* kb = g_kv + (size_t)win * 256 * (2 * DIM) + h * HD;
    const float* vb = kb + DIM;
    #pragma unroll
    for (int it = 0; it < 16; it++) {
        int idx = tid + it * 128;          // 0..2047
        int j = idx >> 3, qd = (idx & 7) * 4;
        float4 kv4 = *(const float4*)(kb + (size_t)j * (2 * DIM) + qd);
        *(float4*)&sK[j * QS + qd] = kv4;
        float4 vv4 = *(const float4*)(vb + (size_t)j * (2 * DIM) + qd);
        sVT[(qd + 0) * PS + j] = vv4.x;
        sVT[(qd + 1) * PS + j] = vv4.y;
        sVT[(qd + 2) * PS + j] = vv4.z;
        sVT[(qd + 3) * PS + j] = vv4.w;
    }
    __syncthreads();

    int warp = tid >> 5, lane = tid & 31;
    int g = lane >> 2, tig = lane & 3;
    int r0 = warp * 16;

    // ---- QK: S = Q @ K^T, full 16x256 in registers
    float acc[32][4];
    #pragma unroll
    for (int nt = 0; nt < 32; nt++)
        #pragma unroll
        for (int i = 0; i < 4; i++) acc[nt][i] = 0.f;

    #pragma unroll
    for (int ks = 0; ks < 4; ks++) {
        int kk = ks * 8;
        float a[4];
        a[0] = sQ[(r0 + g) * QS + kk + tig];
        a[1] = sQ[(r0 + g + 8) * QS + kk + tig];
        a[2] = sQ[(r0 + g) * QS + kk + tig + 4];
        a[3] = sQ[(r0 + g + 8) * QS + kk + tig + 4];
        #pragma unroll
        for (int nt = 0; nt < 32; nt++) {
            float b[2];
            b[0] = sK[(nt * 8 + g) * QS + kk + tig];
            b[1] = sK[(nt * 8 + g) * QS + kk + tig + 4];
            mma_tf32(acc[nt], a, b);
        }
    }

    // ---- scale + bias (acc = acc*SCALE + bias)
    int i_lo = r0 + g, i_hi = i_lo + 8;
    int blo = (i_lo >> 3) * 23 + (i_lo & 7) + 368;   // + 368 - 23*(j>>4) - (j&15)
    int bhi = (i_hi >> 3) * 23 + (i_hi & 7) + 368;
    #pragma unroll
    for (int nt = 0; nt < 32; nt++) {
        int j0 = nt * 8 + tig * 2, j1 = j0 + 1;
        int f0 = 368 - 23 * (j0 >> 4) - (j0 & 15);
        int f1 = 368 - 23 * (j1 >> 4) - (j1 & 15);
        acc[nt][0] = acc[nt][0] * SCALE + sB[blo - 368 + f0];
        acc[nt][1] = acc[nt][1] * SCALE + sB[blo - 368 + f1];
        acc[nt][2] = acc[nt][2] * SCALE + sB[bhi - 368 + f0];
        acc[nt][3] = acc[nt][3] * SCALE + sB[bhi - 368 + f1];
    }

    // ---- softmax (rows i_lo, i_hi), quad-shuffle reductions only
    float mlo = -1e30f, mhi = -1e30f;
    #pragma unroll
    for (int nt = 0; nt < 32; nt++) {
        mlo = fmaxf(mlo, fmaxf(acc[nt][0], acc[nt][1]));
        mhi = fmaxf(mhi, fmaxf(acc[nt][2], acc[nt][3]));
    }
    #pragma unroll
    for (int off = 1; off < 4; off <<= 1) {
        mlo = fmaxf(mlo, __shfl_xor_sync(0xffffffffu, mlo, off));
        mhi = fmaxf(mhi, __shfl_xor_sync(0xffffffffu, mhi, off));
    }
    float slo = 0.f, shi = 0.f;
    #pragma unroll
    for (int nt = 0; nt < 32; nt++) {
        acc[nt][0] = __expf(acc[nt][0] - mlo); slo += acc[nt][0];
        acc[nt][1] = __expf(acc[nt][1] - mlo); slo += acc[nt][1];
        acc[nt][2] = __expf(acc[nt][2] - mhi); shi += acc[nt][2];
        acc[nt][3] = __expf(acc[nt][3] - mhi); shi += acc[nt][3];
    }
    #pragma unroll
    for (int off = 1; off < 4; off <<= 1) {
        slo += __shfl_xor_sync(0xffffffffu, slo, off);
        shi += __shfl_xor_sync(0xffffffffu, shi, off);
    }
    float invlo = 1.0f / slo, invhi = 1.0f / shi;
    #pragma unroll
    for (int nt = 0; nt < 32; nt++) {
        acc[nt][0] *= invlo; acc[nt][1] *= invlo;
        acc[nt][2] *= invhi; acc[nt][3] *= invhi;
    }

    // ---- PV: O = P @ V. P accumulator -> A fragments via in-quad shuffle
    // transpose: c-layout cols {2t, 2t+1} -> a-layout cols {t, t+4}.
    float o[4][4];
    #pragma unroll
    for (int nt = 0; nt < 4; nt++)
        #pragma unroll
        for (int i = 0; i < 4; i++) o[nt][i] = 0.f;

    int src_a = (lane & ~3) | (tig >> 1);
    int src_b = src_a + 2;
    bool odd = (tig & 1);

    #pragma unroll
    for (int kc = 0; kc < 32; kc++) {
        float s0 = __shfl_sync(0xffffffffu, acc[kc][0], src_a);
        float s1 = __shfl_sync(0xffffffffu, acc[kc][1], src_a);
        float s2 = __shfl_sync(0xffffffffu, acc[kc][0], src_b);
        float s3 = __shfl_sync(0xffffffffu, acc[kc][1], src_b);
        float t0 = __shfl_sync(0xffffffffu, acc[kc][2], src_a);
        float t1 = __shfl_sync(0xffffffffu, acc[kc][3], src_a);
        float t2 = __shfl_sync(0xffffffffu, acc[kc][2], src_b);
        float t3 = __shfl_sync(0xffffffffu, acc[kc][3], src_b);
        float a[4];
        a[0] = odd ? s1 : s0;   // P[g   ][8kc + tig]
        a[1] = odd ? t1 : t0;   // P[g+8 ][8kc + tig]
        a[2] = odd ? s3 : s2;   // P[g   ][8kc + tig + 4]
        a[3] = odd ? t3 : t2;   // P[g+8 ][8kc + tig + 4]
        #pragma unroll
        for (int nt = 0; nt < 4; nt++) {
            float b[2];
            b[0] = sVT[(nt * 8 + g) * PS + kc * 8 + tig];
            b[1] = sVT[(nt * 8 + g) * PS + kc * 8 + tig + 4];
            mma_tf32(o[nt], a, b);
        }
    }

    // ---- store O (fp32)
    float* ob = g_ao + (size_t)win * 64 * DIM + h * HD;
    #pragma unroll
    for (int nt = 0; nt < 4; nt++) {
        int col = nt * 8 + tig * 2;
        *(float2*)(ob + (size_t)i_lo * DIM + col) = make_float2(o[nt][0], o[nt][1]);
        *(float2*)(ob + (size_t)i_hi * DIM + col) = make_float2(o[nt][2], o[nt][3]);
    }
}

// ---------------- launch ----------------
extern "C" void kernel_launch(void* const* d_in, const int* in_sizes, int n_in,
                              void* d_out, int out_size)
{
    const float* x     = (const float*)d_in[0];
    const float* x2    = (const float*)d_in[1];
    const float* n1w   = (const float*)d_in[2];
    const float* n1b   = (const float*)d_in[3];
    const float* qkvw  = (const float*)d_in[4];
    const float* qkvb  = (const float*)d_in[5];
    const float* qkv2w = (const float*)d_in[6];
    const float* qkv2b = (const float*)d_in[7];
    const float* relb  = (const float*)d_in[8];
    const float* projw = (const float*)d_in[9];
    const float* projb = (const float*)d_in[10];
    const float* n2w   = (const float*)d_in[11];
    const float* n2b   = (const float*)d_in[12];
    const float* fc1w  = (const float*)d_in[13];
    const float* fc1b  = (const float*)d_in[14];
    const float* fc2w  = (const float*)d_in[15];
    const float* fc2b  = (const float*)d_in[16];
    float* out = (float*)d_out;

    float *p_xn, *p_q, *p_kv, *p_ao, *p_x1, *p_ln2, *p_h;
    cudaGetSymbolAddress((void**)&p_xn,  g_xn);
    cudaGetSymbolAddress((void**)&p_q,   g_q);
    cudaGetSymbolAddress((void**)&p_kv,  g_kv);
    cudaGetSymbolAddress((void**)&p_ao,  g_ao);
    cudaGetSymbolAddress((void**)&p_x1,  g_x1);
    cudaGetSymbolAddress((void**)&p_ln2, g_ln2);
    cudaGetSymbolAddress((void**)&p_h,   g_h);

    const int attn_smem = ATTN_SMEM_FLOATS * (int)sizeof(float);
    cudaFuncSetAttribute(attn_kernel, cudaFuncAttributeMaxDynamicSharedMemorySize, attn_smem);

    // 1. LN1 + window partition
    ln_kernel<0><<<NQTOK, 192>>>(x, n1w, n1b, p_xn);
    // 2. q projection (window order)
    gemm_tf32<0, 192, 192><<<dim3(512, 3), 256>>>(p_xn, qkvw, qkvb, p_q, nullptr);
    // 3. kv projection (gather x2 through 16x16 window partition)
    gemm_tf32<1, 384, 192><<<dim3(2048, 6), 256>>>(x2, qkv2w, qkv2b, p_kv, nullptr);
    // 4. windowed cross attention (register-resident tensor cores)
    attn_kernel<<<dim3(NWIN, HEADS), 128, attn_smem>>>(relb);
    // 5. output projection + shortcut + window reverse -> natural order
    gemm_tf32<2, 192, 192><<<dim3(512, 3), 256>>>(p_ao, projw, projb, p_x1, x);
    // 6. LN2
    ln_kernel<1><<<NQTOK, 192>>>(p_x1, n2w, n2b, p_ln2);
    // 7. fc1 + gelu
    gemm_tf32<3, 768, 192><<<dim3(512, 12), 256>>>(p_ln2, fc1w, fc1b, p_h, nullptr);
    // 8. fc2 + residual -> output
    gemm_tf32<4, 192, 768><<<dim3(512, 3), 256>>>(p_h, fc2w, fc2b, out, p_x1);
}